// round 4
// baseline (speedup 1.0000x reference)
#include <cuda_runtime.h>

#define NB 4
#define NR 2
#define NREF 4
#define IH 320
#define IW 320
#define HW (IH*IW)
#define NPIX (NB*NR*HW)

// Per-render-camera: M = inv(R)*inv(K) (9 floats) then v = inv(R)*t (3 floats)
__device__ float g_renderM[NB*NR][12];
// Per-(b,ref): P = K_ref*R_ref (9) then s = K_ref*t_ref (3)
__device__ float g_refP[NB*NREF][12];

__device__ __forceinline__ void inv3(const float* a, float* o) {
    float c00 = a[4]*a[8] - a[5]*a[7];
    float c10 = a[5]*a[6] - a[3]*a[8];
    float c20 = a[3]*a[7] - a[4]*a[6];
    float det = a[0]*c00 + a[1]*c10 + a[2]*c20;
    float id  = 1.0f/det;
    o[0] = c00*id;
    o[1] = (a[2]*a[7] - a[1]*a[8])*id;
    o[2] = (a[1]*a[5] - a[2]*a[4])*id;
    o[3] = c10*id;
    o[4] = (a[0]*a[8] - a[2]*a[6])*id;
    o[5] = (a[2]*a[3] - a[0]*a[5])*id;
    o[6] = c20*id;
    o[7] = (a[1]*a[6] - a[0]*a[7])*id;
    o[8] = (a[0]*a[4] - a[1]*a[3])*id;
}

__global__ void precompute_kernel(const float* __restrict__ camK,
                                  const float* __restrict__ camW,
                                  const float* __restrict__ camKr,
                                  const float* __restrict__ camWr) {
    int t = threadIdx.x;
    if (t < NB*NR) {
        const float* k = camK + t*9;
        const float* w = camW + t*12;   // rows: [R[i][0..2], t[i]]
        float R[9], tv[3];
        #pragma unroll
        for (int i = 0; i < 3; i++) {
            R[i*3+0] = w[i*4+0];
            R[i*3+1] = w[i*4+1];
            R[i*3+2] = w[i*4+2];
            tv[i]    = w[i*4+3];
        }
        float iK[9], iR[9];
        inv3(k, iK);
        inv3(R, iR);
        float* o = g_renderM[t];
        #pragma unroll
        for (int i = 0; i < 3; i++) {
            #pragma unroll
            for (int j = 0; j < 3; j++)
                o[i*3+j] = iR[i*3+0]*iK[0+j] + iR[i*3+1]*iK[3+j] + iR[i*3+2]*iK[6+j];
            o[9+i] = iR[i*3+0]*tv[0] + iR[i*3+1]*tv[1] + iR[i*3+2]*tv[2];
        }
    } else if (t < NB*NR + NB*NREF) {
        int j = t - NB*NR;
        const float* k = camKr + j*9;
        const float* w = camWr + j*12;
        float* o = g_refP[j];
        #pragma unroll
        for (int i = 0; i < 3; i++) {
            #pragma unroll
            for (int c = 0; c < 3; c++)
                o[i*3+c] = k[i*3+0]*w[0*4+c] + k[i*3+1]*w[1*4+c] + k[i*3+2]*w[2*4+c];
            o[9+i] = k[i*3+0]*w[0*4+3] + k[i*3+1]*w[1*4+3] + k[i*3+2]*w[2*4+3];
        }
    }
}

__global__ void __launch_bounds__(256) render_kernel(
    const float* __restrict__ depth,
    const float* __restrict__ image_ref,
    const float* __restrict__ background,
    float* __restrict__ out)
{
    int idx = blockIdx.x * blockDim.x + threadIdx.x;
    if (idx >= NPIX) return;

    int pix = idx % HW;
    int cam = idx / HW;       // = b*NR + n
    int b   = cam / NR;
    int obase = cam*3*HW + pix;

    float d = depth[idx];
    if (!(d > 0.0f)) {
        out[obase]        = background[obase];
        out[obase + HW]   = background[obase + HW];
        out[obase + 2*HW] = background[obase + 2*HW];
        return;
    }

    float fx = (float)(pix % IW);
    float fy = (float)(pix / IW);
    const float* M = g_renderM[cam];
    float nd = -d;
    float px = nd*(M[0]*fx + M[1]*fy + M[2]) - M[9];
    float py = nd*(M[3]*fx + M[4]*fy + M[5]) - M[10];
    float pz = nd*(M[6]*fx + M[7]*fy + M[8]) - M[11];

    float r0 = 0.0f, r1 = 0.0f, r2 = 0.0f;

    #pragma unroll
    for (int r = 0; r < NREF; r++) {
        const float* P = g_refP[b*NREF + r];
        float qx = P[0]*px + P[1]*py + P[2]*pz + P[9];
        float qy = P[3]*px + P[4]*py + P[5]*pz + P[10];
        float qz = P[6]*px + P[7]*py + P[8]*pz + P[11];
        float iz = __frcp_rn(qz);
        float u = qx*iz;
        float v = qy*iz;

        float x0 = floorf(u);
        float y0 = floorf(v);
        float wx = u - x0;
        float wy = v - y0;
        float x1 = x0 + 1.0f;
        float y1 = y0 + 1.0f;

        const float* fm = image_ref + (size_t)(b*NREF + r)*3*HW;

        float w00 = (1.0f-wx)*(1.0f-wy);
        float w01 = wx*(1.0f-wy);
        float w10 = (1.0f-wx)*wy;
        float w11 = wx*wy;

        bool vx0 = (x0 >= 0.0f) && (x0 <= (float)(IW-1));
        bool vx1 = (x1 >= 0.0f) && (x1 <= (float)(IW-1));
        bool vy0 = (y0 >= 0.0f) && (y0 <= (float)(IH-1));
        bool vy1 = (y1 >= 0.0f) && (y1 <= (float)(IH-1));

        int xi0 = (int)fminf(fmaxf(x0, 0.0f), (float)(IW-1));
        int xi1 = (int)fminf(fmaxf(x1, 0.0f), (float)(IW-1));
        int yi0 = (int)fminf(fmaxf(y0, 0.0f), (float)(IH-1));
        int yi1 = (int)fminf(fmaxf(y1, 0.0f), (float)(IH-1));

        if (vx0 && vy0) {
            int o = yi0*IW + xi0;
            r0 += w00*__ldg(fm + o);
            r1 += w00*__ldg(fm + HW + o);
            r2 += w00*__ldg(fm + 2*HW + o);
        }
        if (vx1 && vy0) {
            int o = yi0*IW + xi1;
            r0 += w01*__ldg(fm + o);
            r1 += w01*__ldg(fm + HW + o);
            r2 += w01*__ldg(fm + 2*HW + o);
        }
        if (vx0 && vy1) {
            int o = yi1*IW + xi0;
            r0 += w10*__ldg(fm + o);
            r1 += w10*__ldg(fm + HW + o);
            r2 += w10*__ldg(fm + 2*HW + o);
        }
        if (vx1 && vy1) {
            int o = yi1*IW + xi1;
            r0 += w11*__ldg(fm + o);
            r1 += w11*__ldg(fm + HW + o);
            r2 += w11*__ldg(fm + 2*HW + o);
        }
    }

    const float sc = 1.0f / (float)NREF;
    out[obase]        = r0*sc;
    out[obase + HW]   = r1*sc;
    out[obase + 2*HW] = r2*sc;
}

extern "C" void kernel_launch(void* const* d_in, const int* in_sizes, int n_in,
                              void* d_out, int out_size) {
    const float* depth      = (const float*)d_in[0];
    const float* cam_K      = (const float*)d_in[1];
    const float* cam_W      = (const float*)d_in[2];
    const float* image_ref  = (const float*)d_in[3];
    const float* background = (const float*)d_in[4];
    // d_in[5] = cube_diagonal : divide/multiply cancels, unused
    const float* cam_K_ref  = (const float*)d_in[6];
    const float* cam_W_ref  = (const float*)d_in[7];

    precompute_kernel<<<1, 32>>>(cam_K, cam_W, cam_K_ref, cam_W_ref);
    int n = NPIX;
    render_kernel<<<(n + 255) / 256, 256>>>(depth, image_ref, background, (float*)d_out);
}

// round 5
// speedup vs baseline: 1.3183x; 1.3183x over previous
#include <cuda_runtime.h>

#define NB 4
#define NR 2
#define NREF 4
#define IH 320
#define IW 320
#define HW (IH*IW)
#define NPIX (NB*NR*HW)
#define NIMG (NB*NREF)

// Per-render-camera: M = inv(R)*inv(K) (9 floats) then v = inv(R)*t (3 floats)
__device__ float g_renderM[NB*NR][12];
// Per-(b,ref): P = K_ref*R_ref (9) then s = K_ref*t_ref (3)
__device__ float g_refP[NB*NREF][12];
// Channel-interleaved copy of image_ref: (img, y, x) -> float4(r,g,b,0)
__device__ float4 g_img4[NIMG*HW];

__device__ __forceinline__ void inv3(const float* a, float* o) {
    float c00 = a[4]*a[8] - a[5]*a[7];
    float c10 = a[5]*a[6] - a[3]*a[8];
    float c20 = a[3]*a[7] - a[4]*a[6];
    float det = a[0]*c00 + a[1]*c10 + a[2]*c20;
    float id  = 1.0f/det;
    o[0] = c00*id;
    o[1] = (a[2]*a[7] - a[1]*a[8])*id;
    o[2] = (a[1]*a[5] - a[2]*a[4])*id;
    o[3] = c10*id;
    o[4] = (a[0]*a[8] - a[2]*a[6])*id;
    o[5] = (a[2]*a[3] - a[0]*a[5])*id;
    o[6] = c20*id;
    o[7] = (a[1]*a[6] - a[0]*a[7])*id;
    o[8] = (a[0]*a[4] - a[1]*a[3])*id;
}

__global__ void precompute_kernel(const float* __restrict__ camK,
                                  const float* __restrict__ camW,
                                  const float* __restrict__ camKr,
                                  const float* __restrict__ camWr) {
    int t = threadIdx.x;
    if (t < NB*NR) {
        const float* k = camK + t*9;
        const float* w = camW + t*12;   // rows: [R[i][0..2], t[i]]
        float R[9], tv[3];
        #pragma unroll
        for (int i = 0; i < 3; i++) {
            R[i*3+0] = w[i*4+0];
            R[i*3+1] = w[i*4+1];
            R[i*3+2] = w[i*4+2];
            tv[i]    = w[i*4+3];
        }
        float iK[9], iR[9];
        inv3(k, iK);
        inv3(R, iR);
        float* o = g_renderM[t];
        #pragma unroll
        for (int i = 0; i < 3; i++) {
            #pragma unroll
            for (int j = 0; j < 3; j++)
                o[i*3+j] = iR[i*3+0]*iK[0+j] + iR[i*3+1]*iK[3+j] + iR[i*3+2]*iK[6+j];
            o[9+i] = iR[i*3+0]*tv[0] + iR[i*3+1]*tv[1] + iR[i*3+2]*tv[2];
        }
    } else if (t < NB*NR + NB*NREF) {
        int j = t - NB*NR;
        const float* k = camKr + j*9;
        const float* w = camWr + j*12;
        float* o = g_refP[j];
        #pragma unroll
        for (int i = 0; i < 3; i++) {
            #pragma unroll
            for (int c = 0; c < 3; c++)
                o[i*3+c] = k[i*3+0]*w[0*4+c] + k[i*3+1]*w[1*4+c] + k[i*3+2]*w[2*4+c];
            o[9+i] = k[i*3+0]*w[0*4+3] + k[i*3+1]*w[1*4+3] + k[i*3+2]*w[2*4+3];
        }
    }
}

// Planar (img,c,y,x) -> AoS float4 (img,y,x). Coalesced reads (3 planes) and
// fully coalesced 16B writes.
__global__ void __launch_bounds__(256) interleave_kernel(const float* __restrict__ src) {
    int i = blockIdx.x * blockDim.x + threadIdx.x;
    if (i >= NIMG*HW) return;
    int img = i / HW;
    int pix = i - img*HW;
    const float* p = src + (size_t)img*3*HW + pix;
    g_img4[i] = make_float4(__ldg(p), __ldg(p + HW), __ldg(p + 2*HW), 0.0f);
}

__global__ void __launch_bounds__(256) render_kernel(
    const float* __restrict__ depth,
    const float* __restrict__ background,
    float* __restrict__ out)
{
    int idx = blockIdx.x * blockDim.x + threadIdx.x;
    if (idx >= NPIX) return;

    int pix = idx % HW;
    int cam = idx / HW;       // = b*NR + n
    int b   = cam / NR;
    int obase = cam*3*HW + pix;

    float d = depth[idx];
    if (!(d > 0.0f)) {
        out[obase]        = background[obase];
        out[obase + HW]   = background[obase + HW];
        out[obase + 2*HW] = background[obase + 2*HW];
        return;
    }

    float fx = (float)(pix % IW);
    float fy = (float)(pix / IW);
    const float* M = g_renderM[cam];
    float nd = -d;
    float px = nd*(M[0]*fx + M[1]*fy + M[2]) - M[9];
    float py = nd*(M[3]*fx + M[4]*fy + M[5]) - M[10];
    float pz = nd*(M[6]*fx + M[7]*fy + M[8]) - M[11];

    float r0 = 0.0f, r1 = 0.0f, r2 = 0.0f;

    #pragma unroll
    for (int r = 0; r < NREF; r++) {
        const float* P = g_refP[b*NREF + r];
        float qx = P[0]*px + P[1]*py + P[2]*pz + P[9];
        float qy = P[3]*px + P[4]*py + P[5]*pz + P[10];
        float qz = P[6]*px + P[7]*py + P[8]*pz + P[11];
        float iz = __frcp_rn(qz);
        float u = qx*iz;
        float v = qy*iz;

        float x0 = floorf(u);
        float y0 = floorf(v);
        float wx = u - x0;
        float wy = v - y0;
        float x1 = x0 + 1.0f;
        float y1 = y0 + 1.0f;

        const float4* fm = g_img4 + (size_t)(b*NREF + r)*HW;

        float w00 = (1.0f-wx)*(1.0f-wy);
        float w01 = wx*(1.0f-wy);
        float w10 = (1.0f-wx)*wy;
        float w11 = wx*wy;

        bool vx0 = (x0 >= 0.0f) && (x0 <= (float)(IW-1));
        bool vx1 = (x1 >= 0.0f) && (x1 <= (float)(IW-1));
        bool vy0 = (y0 >= 0.0f) && (y0 <= (float)(IH-1));
        bool vy1 = (y1 >= 0.0f) && (y1 <= (float)(IH-1));

        int xi0 = (int)fminf(fmaxf(x0, 0.0f), (float)(IW-1));
        int xi1 = (int)fminf(fmaxf(x1, 0.0f), (float)(IW-1));
        int yi0 = (int)fminf(fmaxf(y0, 0.0f), (float)(IH-1));
        int yi1 = (int)fminf(fmaxf(y1, 0.0f), (float)(IH-1));

        if (vx0 && vy0) {
            float4 c = __ldg(fm + (yi0*IW + xi0));
            r0 += w00*c.x; r1 += w00*c.y; r2 += w00*c.z;
        }
        if (vx1 && vy0) {
            float4 c = __ldg(fm + (yi0*IW + xi1));
            r0 += w01*c.x; r1 += w01*c.y; r2 += w01*c.z;
        }
        if (vx0 && vy1) {
            float4 c = __ldg(fm + (yi1*IW + xi0));
            r0 += w10*c.x; r1 += w10*c.y; r2 += w10*c.z;
        }
        if (vx1 && vy1) {
            float4 c = __ldg(fm + (yi1*IW + xi1));
            r0 += w11*c.x; r1 += w11*c.y; r2 += w11*c.z;
        }
    }

    const float sc = 1.0f / (float)NREF;
    out[obase]        = r0*sc;
    out[obase + HW]   = r1*sc;
    out[obase + 2*HW] = r2*sc;
}

extern "C" void kernel_launch(void* const* d_in, const int* in_sizes, int n_in,
                              void* d_out, int out_size) {
    const float* depth      = (const float*)d_in[0];
    const float* cam_K      = (const float*)d_in[1];
    const float* cam_W      = (const float*)d_in[2];
    const float* image_ref  = (const float*)d_in[3];
    const float* background = (const float*)d_in[4];
    // d_in[5] = cube_diagonal : divide/multiply cancels, unused
    const float* cam_K_ref  = (const float*)d_in[6];
    const float* cam_W_ref  = (const float*)d_in[7];

    precompute_kernel<<<1, 32>>>(cam_K, cam_W, cam_K_ref, cam_W_ref);
    interleave_kernel<<<(NIMG*HW + 255) / 256, 256>>>(image_ref);
    render_kernel<<<(NPIX + 255) / 256, 256>>>(depth, background, (float*)d_out);
}